// round 1
// baseline (speedup 1.0000x reference)
#include <cuda_runtime.h>
#include <math.h>

// Problem constants (fixed by the reference).
static constexpr int M = 8192;   // nnodes
static constexpr int K = 512;    // feature dim
static constexpr float NEG_SLOPE = 0.01f;

// Normalized proto scratch (16 MB). __device__ global: allocation-free per harness rules.
__device__ float g_pn[M * K];

// ---------------------------------------------------------------------------
// Kernel 1: row L2-normalize proto -> g_pn. One block per row, 128 threads,
// one float4 per thread (K/4 = 128).
// ---------------------------------------------------------------------------
__global__ void __launch_bounds__(128) normalize_rows(const float* __restrict__ proto) {
    __shared__ float red[4];
    const int row = blockIdx.x;
    const int t = threadIdx.x;

    float4 v = reinterpret_cast<const float4*>(proto)[row * (K / 4) + t];
    float ss = v.x * v.x + v.y * v.y + v.z * v.z + v.w * v.w;

    #pragma unroll
    for (int o = 16; o > 0; o >>= 1)
        ss += __shfl_xor_sync(0xffffffffu, ss, o);
    if ((t & 31) == 0) red[t >> 5] = ss;
    __syncthreads();

    const float total = red[0] + red[1] + red[2] + red[3];
    const float inv = 1.0f / fmaxf(sqrtf(total), 1e-12f);  // matches torch F.normalize eps

    float4 o4 = make_float4(v.x * inv, v.y * inv, v.z * inv, v.w * inv);
    reinterpret_cast<float4*>(g_pn)[row * (K / 4) + t] = o4;
}

// ---------------------------------------------------------------------------
// Kernel 2: C = leaky_relu(Pn * Pn^T), exploiting symmetry.
// 128x128 block tile, BK=16, 8x8 per thread, 256 threads.
// Blocks with bx < by exit; bx > by blocks also write the mirrored tile.
// ---------------------------------------------------------------------------
static constexpr int BM = 128, BN = 128, BK = 16, TM = 8, TN = 8;

__device__ __forceinline__ float leaky(float v) {
    return v >= 0.0f ? v : NEG_SLOPE * v;
}

__global__ void __launch_bounds__(256) sgemm_sym(float* __restrict__ C) {
    const int bx = blockIdx.x;
    const int by = blockIdx.y;
    if (bx < by) return;  // upper-triangle (block-level) only

    // +4 pad keeps 16B alignment for float4 LDS while breaking STS bank conflicts.
    __shared__ float As[BK][BM + 4];
    __shared__ float Bs[BK][BN + 4];

    const int tid = threadIdx.x;
    const int tCol = tid & 15;   // 0..15
    const int tRow = tid >> 4;   // 0..15

    const float* __restrict__ Abase = g_pn + (size_t)by * BM * K;
    const float* __restrict__ Bbase = g_pn + (size_t)bx * BN * K;

    float acc[TM][TN];
    #pragma unroll
    for (int i = 0; i < TM; i++)
        #pragma unroll
        for (int j = 0; j < TN; j++) acc[i][j] = 0.0f;

    for (int k0 = 0; k0 < K; k0 += BK) {
        // Cooperative load: 128 rows x 16 cols per operand = 512 float4; 2 per thread.
        #pragma unroll
        for (int i = 0; i < 2; i++) {
            const int idx = tid + i * 256;     // 0..511
            const int r = idx >> 2;            // 0..127
            const int c4 = (idx & 3) << 2;     // 0,4,8,12

            float4 a = *reinterpret_cast<const float4*>(Abase + (size_t)r * K + k0 + c4);
            As[c4 + 0][r] = a.x; As[c4 + 1][r] = a.y;
            As[c4 + 2][r] = a.z; As[c4 + 3][r] = a.w;

            float4 b = *reinterpret_cast<const float4*>(Bbase + (size_t)r * K + k0 + c4);
            Bs[c4 + 0][r] = b.x; Bs[c4 + 1][r] = b.y;
            Bs[c4 + 2][r] = b.z; Bs[c4 + 3][r] = b.w;
        }
        __syncthreads();

        #pragma unroll
        for (int kk = 0; kk < BK; kk++) {
            float a_frag[TM], b_frag[TN];
            float4 a0 = *reinterpret_cast<const float4*>(&As[kk][tRow * TM]);
            float4 a1 = *reinterpret_cast<const float4*>(&As[kk][tRow * TM + 4]);
            float4 b0 = *reinterpret_cast<const float4*>(&Bs[kk][tCol * TN]);
            float4 b1 = *reinterpret_cast<const float4*>(&Bs[kk][tCol * TN + 4]);
            a_frag[0] = a0.x; a_frag[1] = a0.y; a_frag[2] = a0.z; a_frag[3] = a0.w;
            a_frag[4] = a1.x; a_frag[5] = a1.y; a_frag[6] = a1.z; a_frag[7] = a1.w;
            b_frag[0] = b0.x; b_frag[1] = b0.y; b_frag[2] = b0.z; b_frag[3] = b0.w;
            b_frag[4] = b1.x; b_frag[5] = b1.y; b_frag[6] = b1.z; b_frag[7] = b1.w;

            #pragma unroll
            for (int i = 0; i < TM; i++)
                #pragma unroll
                for (int j = 0; j < TN; j++)
                    acc[i][j] = fmaf(a_frag[i], b_frag[j], acc[i][j]);
        }
        __syncthreads();
    }

    const int rBase = by * BM + tRow * TM;
    const int cBase = bx * BN + tCol * TN;

    // Normal tile: coalesced float4 writes.
    #pragma unroll
    for (int i = 0; i < TM; i++) {
        float4 v0 = make_float4(leaky(acc[i][0]), leaky(acc[i][1]),
                                leaky(acc[i][2]), leaky(acc[i][3]));
        float4 v1 = make_float4(leaky(acc[i][4]), leaky(acc[i][5]),
                                leaky(acc[i][6]), leaky(acc[i][7]));
        float* p = C + (size_t)(rBase + i) * M + cBase;
        *reinterpret_cast<float4*>(p) = v0;
        *reinterpret_cast<float4*>(p + 4) = v1;
    }

    // Mirror tile (transpose) for off-diagonal blocks.
    if (bx != by) {
        #pragma unroll
        for (int j = 0; j < TN; j++) {
            float4 w0 = make_float4(leaky(acc[0][j]), leaky(acc[1][j]),
                                    leaky(acc[2][j]), leaky(acc[3][j]));
            float4 w1 = make_float4(leaky(acc[4][j]), leaky(acc[5][j]),
                                    leaky(acc[6][j]), leaky(acc[7][j]));
            float* p = C + (size_t)(cBase + j) * M + rBase;
            *reinterpret_cast<float4*>(p) = w0;
            *reinterpret_cast<float4*>(p + 4) = w1;
        }
    }
}

// ---------------------------------------------------------------------------
// Launch. Inputs (metadata order): d_in[0] = x (UNUSED by the reference),
// d_in[1] = proto (8192*512 f32). Output: 8192*8192 f32.
// ---------------------------------------------------------------------------
extern "C" void kernel_launch(void* const* d_in, const int* in_sizes, int n_in,
                              void* d_out, int out_size) {
    (void)in_sizes; (void)n_in; (void)out_size;
    const float* proto = (const float*)d_in[1];
    float* C = (float*)d_out;

    normalize_rows<<<M, 128>>>(proto);
    sgemm_sym<<<dim3(M / BN, M / BM), 256>>>(C);
}

// round 10
// speedup vs baseline: 2.1491x; 2.1491x over previous
#include <cuda_runtime.h>
#include <cuda_bf16.h>
#include <stdint.h>
#include <math.h>

// ---------------------------------------------------------------------------
// Problem constants
// ---------------------------------------------------------------------------
static constexpr int M = 8192;   // nnodes
static constexpr int K = 512;    // feature dim
static constexpr float NEG_SLOPE = 0.01f;

// Split-bf16 representation of the normalized proto matrix (8 MB + 8 MB).
__device__ __nv_bfloat16 g_hi[(size_t)M * K];
__device__ __nv_bfloat16 g_lo[(size_t)M * K];

// ---------------------------------------------------------------------------
// PTX helpers — ONLY plain-target (compute_103-legal) instructions:
// ldmatrix (sm_75+), mma.sync bf16 (sm_80+), cp.async (sm_80+).
// ---------------------------------------------------------------------------
__device__ __forceinline__ uint32_t smem_u32(const void* p) {
    uint32_t a;
    asm("{ .reg .u64 t; cvta.to.shared.u64 t, %1; cvt.u32.u64 %0, t; }"
        : "=r"(a) : "l"(p));
    return a;
}

__device__ __forceinline__ void ldsm_x4(uint32_t& r0, uint32_t& r1,
                                        uint32_t& r2, uint32_t& r3, uint32_t addr) {
    asm volatile("ldmatrix.sync.aligned.m8n8.x4.shared.b16 {%0,%1,%2,%3}, [%4];"
                 : "=r"(r0), "=r"(r1), "=r"(r2), "=r"(r3) : "r"(addr));
}
__device__ __forceinline__ void ldsm_x2(uint32_t& r0, uint32_t& r1, uint32_t addr) {
    asm volatile("ldmatrix.sync.aligned.m8n8.x2.shared.b16 {%0,%1}, [%2];"
                 : "=r"(r0), "=r"(r1) : "r"(addr));
}

__device__ __forceinline__ void mma_bf16(float* c,
                                         uint32_t a0, uint32_t a1, uint32_t a2, uint32_t a3,
                                         uint32_t b0, uint32_t b1) {
    asm volatile(
        "mma.sync.aligned.m16n8k16.row.col.f32.bf16.bf16.f32 "
        "{%0,%1,%2,%3}, {%4,%5,%6,%7}, {%8,%9}, {%0,%1,%2,%3};"
        : "+f"(c[0]), "+f"(c[1]), "+f"(c[2]), "+f"(c[3])
        : "r"(a0), "r"(a1), "r"(a2), "r"(a3), "r"(b0), "r"(b1));
}

__device__ __forceinline__ void cp_async16(uint32_t saddr, const void* gptr) {
    asm volatile("cp.async.cg.shared.global [%0], [%1], 16;"
                 :: "r"(saddr), "l"(gptr));
}
__device__ __forceinline__ void cp_commit() {
    asm volatile("cp.async.commit_group;" ::: "memory");
}
template <int N>
__device__ __forceinline__ void cp_wait() {
    asm volatile("cp.async.wait_group %0;" :: "n"(N) : "memory");
}

// ---------------------------------------------------------------------------
// Kernel 1: row L2-normalize + split into bf16 hi/lo.
// ---------------------------------------------------------------------------
__global__ void __launch_bounds__(128) normalize_split(const float* __restrict__ proto) {
    __shared__ float red[4];
    const int row = blockIdx.x;
    const int t = threadIdx.x;

    float4 v = reinterpret_cast<const float4*>(proto)[row * (K / 4) + t];
    float ss = v.x * v.x + v.y * v.y + v.z * v.z + v.w * v.w;
    #pragma unroll
    for (int o = 16; o > 0; o >>= 1) ss += __shfl_xor_sync(0xffffffffu, ss, o);
    if ((t & 31) == 0) red[t >> 5] = ss;
    __syncthreads();
    const float total = red[0] + red[1] + red[2] + red[3];
    const float inv = 1.0f / fmaxf(sqrtf(total), 1e-12f);

    float f[4] = {v.x * inv, v.y * inv, v.z * inv, v.w * inv};
    __nv_bfloat16 hi[4], lo[4];
    #pragma unroll
    for (int i = 0; i < 4; i++) {
        hi[i] = __float2bfloat16(f[i]);
        lo[i] = __float2bfloat16(f[i] - __bfloat162float(hi[i]));
    }
    const size_t base2 = (size_t)row * (K / 2) + t * 2;
    __nv_bfloat162* h2 = reinterpret_cast<__nv_bfloat162*>(g_hi);
    __nv_bfloat162* l2 = reinterpret_cast<__nv_bfloat162*>(g_lo);
    h2[base2 + 0] = __nv_bfloat162(hi[0], hi[1]);
    h2[base2 + 1] = __nv_bfloat162(hi[2], hi[3]);
    l2[base2 + 0] = __nv_bfloat162(lo[0], lo[1]);
    l2[base2 + 1] = __nv_bfloat162(lo[2], lo[3]);
}

// ---------------------------------------------------------------------------
// Kernel 2: bf16 mma.sync GEMM, 128x128 tile, BK=32, 2-stage cp.async pipe.
// D = Ahi*Bhi^T + Ahi*Blo^T + Alo*Bhi^T (fp32 acc), symmetric skip + mirror.
// 8 warps in 4(M) x 2(N); warp tile 32x64 = 2x8 m16n8 mma tiles.
// ---------------------------------------------------------------------------
static constexpr int BM = 128, BN = 128, BK = 32;
static constexpr int NCHUNK = K / BK;                 // 16
static constexpr int LDS_STRIDE_B = 80;               // bytes per smem row (40 bf16)
static constexpr int TILE_BYTES = BM * LDS_STRIDE_B;  // 10240
static constexpr int STAGE_BYTES = 4 * TILE_BYTES;    // Ahi,Alo,Bhi,Blo = 40960
static constexpr int SMEM_TOTAL = 2 * STAGE_BYTES;    // 81920

__device__ __forceinline__ float leaky(float v) {
    return v >= 0.0f ? v : NEG_SLOPE * v;
}

// Issue cp.async for one 4-tile chunk (Ahi,Alo,Bhi,Blo; 128 rows x 32 bf16 each).
// 2048 x 16B over 256 threads = 8 per thread.
__device__ __forceinline__ void load_chunk(uint32_t sbase, int rowA, int rowB,
                                           int k0, int tid) {
    #pragma unroll
    for (int i = 0; i < 8; i++) {
        const int idx = tid + i * 256;        // 0..2047
        const int t = idx >> 9;               // tile 0..3
        const int idx2 = idx & 511;
        const int row = idx2 >> 2;            // 0..127
        const int c8 = idx2 & 3;              // 16B unit within 64B of row data
        const int r0 = (t < 2) ? rowA : rowB;
        const __nv_bfloat16* src = (t & 1) ? g_lo : g_hi;
        const void* g = (const void*)(src + (size_t)(r0 + row) * K + k0 + c8 * 8);
        const uint32_t s = sbase + t * TILE_BYTES + row * LDS_STRIDE_B + c8 * 16;
        cp_async16(s, g);
    }
}

__global__ void __launch_bounds__(256, 1) gemm_mma(float* __restrict__ C) {
    const int bx = blockIdx.x;
    const int by = blockIdx.y;
    if (bx < by) return;  // block-level upper triangle only

    extern __shared__ char smem[];
    const uint32_t sb = smem_u32(smem);
    const int tid = threadIdx.x;
    const int wid = tid >> 5;
    const int lane = tid & 31;
    const int wm = wid & 3;   // 0..3 -> 32-row slab
    const int wn = wid >> 2;  // 0..1 -> 64-col slab

    const int rowA = by * BM;
    const int rowB = bx * BN;

    float acc[2][8][4] = {};

    load_chunk(sb, rowA, rowB, 0, tid);
    cp_commit();

    for (int c = 0; c < NCHUNK; c++) {
        const int stage = c & 1;
        if (c + 1 < NCHUNK) {
            load_chunk(sb + ((c + 1) & 1) * STAGE_BYTES, rowA, rowB,
                       (c + 1) * BK, tid);
            cp_commit();
            cp_wait<1>();
        } else {
            cp_wait<0>();
        }
        __syncthreads();

        const uint32_t Ah = sb + stage * STAGE_BYTES;
        const uint32_t Al = Ah + TILE_BYTES;
        const uint32_t Bh = Ah + 2 * TILE_BYTES;
        const uint32_t Bl = Ah + 3 * TILE_BYTES;

        #pragma unroll
        for (int ks = 0; ks < 2; ks++) {
            uint32_t ah[2][4], al[2][4];
            #pragma unroll
            for (int mt = 0; mt < 2; mt++) {
                const int r = wm * 32 + mt * 16 + (lane & 15);
                const int colb = (ks * 16 + ((lane >> 4) << 3)) * 2;
                const uint32_t off = r * LDS_STRIDE_B + colb;
                ldsm_x4(ah[mt][0], ah[mt][1], ah[mt][2], ah[mt][3], Ah + off);
                ldsm_x4(al[mt][0], al[mt][1], al[mt][2], al[mt][3], Al + off);
            }
            uint32_t bh[8][2], bl[8][2];
            #pragma unroll
            for (int nt = 0; nt < 8; nt++) {
                const int r = wn * 64 + nt * 8 + (lane & 7);
                const int colb = (ks * 16 + (((lane >> 3) & 1) << 3)) * 2;
                const uint32_t off = r * LDS_STRIDE_B + colb;
                ldsm_x2(bh[nt][0], bh[nt][1], Bh + off);
                ldsm_x2(bl[nt][0], bl[nt][1], Bl + off);
            }
            #pragma unroll
            for (int mt = 0; mt < 2; mt++)
                #pragma unroll
                for (int nt = 0; nt < 8; nt++) {
                    mma_bf16(acc[mt][nt], ah[mt][0], ah[mt][1], ah[mt][2], ah[mt][3],
                             bh[nt][0], bh[nt][1]);
                    mma_bf16(acc[mt][nt], ah[mt][0], ah[mt][1], ah[mt][2], ah[mt][3],
                             bl[nt][0], bl[nt][1]);
                    mma_bf16(acc[mt][nt], al[mt][0], al[mt][1], al[mt][2], al[mt][3],
                             bh[nt][0], bh[nt][1]);
                }
        }
        __syncthreads();  // all reads of this stage done before its next overwrite
    }

    // Epilogue: mma acc layout: c0,c1 -> (row, col+{0,1}); c2,c3 -> (row+8, ...).
    const int gr = lane >> 2;
    const int gc = (lane & 3) * 2;
    #pragma unroll
    for (int mt = 0; mt < 2; mt++) {
        #pragma unroll
        for (int nt = 0; nt < 8; nt++) {
            const float* a = acc[mt][nt];
            const int row = by * BM + wm * 32 + mt * 16 + gr;
            const int col = bx * BN + wn * 64 + nt * 8 + gc;
            const float v0 = leaky(a[0]), v1 = leaky(a[1]);
            const float v2 = leaky(a[2]), v3 = leaky(a[3]);
            *reinterpret_cast<float2*>(C + (size_t)row * M + col) = make_float2(v0, v1);
            *reinterpret_cast<float2*>(C + (size_t)(row + 8) * M + col) = make_float2(v2, v3);
            if (bx != by) {
                C[(size_t)col * M + row] = v0;
                C[(size_t)(col + 1) * M + row] = v1;
                C[(size_t)col * M + row + 8] = v2;
                C[(size_t)(col + 1) * M + row + 8] = v3;
            }
        }
    }
}

// ---------------------------------------------------------------------------
// Launch. d_in[0] = x (unused), d_in[1] = proto. Output 8192x8192 f32.
// ---------------------------------------------------------------------------
extern "C" void kernel_launch(void* const* d_in, const int* in_sizes, int n_in,
                              void* d_out, int out_size) {
    (void)in_sizes; (void)n_in; (void)out_size;
    const float* proto = (const float*)d_in[1];
    float* C = (float*)d_out;

    cudaFuncSetAttribute(gemm_mma, cudaFuncAttributeMaxDynamicSharedMemorySize,
                         SMEM_TOTAL);
    normalize_split<<<M, 128>>>(proto);
    gemm_mma<<<dim3(M / BN, M / BM), 256, SMEM_TOTAL>>>(C);
}

// round 11
// speedup vs baseline: 2.5225x; 1.1738x over previous
#include <cuda_runtime.h>
#include <cuda_bf16.h>
#include <stdint.h>
#include <math.h>

// ---------------------------------------------------------------------------
// Problem constants
// ---------------------------------------------------------------------------
static constexpr int M = 8192;   // nnodes
static constexpr int K = 512;    // feature dim
static constexpr float NEG_SLOPE = 0.01f;

// Split-bf16 representation of the normalized proto matrix (8 MB + 8 MB).
__device__ __nv_bfloat16 g_hi[(size_t)M * K];
__device__ __nv_bfloat16 g_lo[(size_t)M * K];

// ---------------------------------------------------------------------------
// PTX helpers — ONLY plain-target (compute_103-legal) instructions:
// ldmatrix (sm_75+), mma.sync bf16 (sm_80+), cp.async (sm_80+).
// ---------------------------------------------------------------------------
__device__ __forceinline__ uint32_t smem_u32(const void* p) {
    uint32_t a;
    asm("{ .reg .u64 t; cvta.to.shared.u64 t, %1; cvt.u32.u64 %0, t; }"
        : "=r"(a) : "l"(p));
    return a;
}

__device__ __forceinline__ void ldsm_x4(uint32_t& r0, uint32_t& r1,
                                        uint32_t& r2, uint32_t& r3, uint32_t addr) {
    asm volatile("ldmatrix.sync.aligned.m8n8.x4.shared.b16 {%0,%1,%2,%3}, [%4];"
                 : "=r"(r0), "=r"(r1), "=r"(r2), "=r"(r3) : "r"(addr));
}
__device__ __forceinline__ void ldsm_x2(uint32_t& r0, uint32_t& r1, uint32_t addr) {
    asm volatile("ldmatrix.sync.aligned.m8n8.x2.shared.b16 {%0,%1}, [%2];"
                 : "=r"(r0), "=r"(r1) : "r"(addr));
}

__device__ __forceinline__ void mma_bf16(float* c,
                                         uint32_t a0, uint32_t a1, uint32_t a2, uint32_t a3,
                                         uint32_t b0, uint32_t b1) {
    asm volatile(
        "mma.sync.aligned.m16n8k16.row.col.f32.bf16.bf16.f32 "
        "{%0,%1,%2,%3}, {%4,%5,%6,%7}, {%8,%9}, {%0,%1,%2,%3};"
        : "+f"(c[0]), "+f"(c[1]), "+f"(c[2]), "+f"(c[3])
        : "r"(a0), "r"(a1), "r"(a2), "r"(a3), "r"(b0), "r"(b1));
}

__device__ __forceinline__ void cp_async16(uint32_t saddr, const void* gptr) {
    asm volatile("cp.async.cg.shared.global [%0], [%1], 16;"
                 :: "r"(saddr), "l"(gptr));
}
__device__ __forceinline__ void cp_commit() {
    asm volatile("cp.async.commit_group;" ::: "memory");
}
template <int N>
__device__ __forceinline__ void cp_wait() {
    asm volatile("cp.async.wait_group %0;" :: "n"(N) : "memory");
}

// ---------------------------------------------------------------------------
// Kernel 1: row L2-normalize + split into bf16 hi/lo.
// ---------------------------------------------------------------------------
__global__ void __launch_bounds__(128) normalize_split(const float* __restrict__ proto) {
    __shared__ float red[4];
    const int row = blockIdx.x;
    const int t = threadIdx.x;

    float4 v = reinterpret_cast<const float4*>(proto)[row * (K / 4) + t];
    float ss = v.x * v.x + v.y * v.y + v.z * v.z + v.w * v.w;
    #pragma unroll
    for (int o = 16; o > 0; o >>= 1) ss += __shfl_xor_sync(0xffffffffu, ss, o);
    if ((t & 31) == 0) red[t >> 5] = ss;
    __syncthreads();
    const float total = red[0] + red[1] + red[2] + red[3];
    const float inv = 1.0f / fmaxf(sqrtf(total), 1e-12f);

    float f[4] = {v.x * inv, v.y * inv, v.z * inv, v.w * inv};
    __nv_bfloat16 hi[4], lo[4];
    #pragma unroll
    for (int i = 0; i < 4; i++) {
        hi[i] = __float2bfloat16(f[i]);
        lo[i] = __float2bfloat16(f[i] - __bfloat162float(hi[i]));
    }
    const size_t base2 = (size_t)row * (K / 2) + t * 2;
    __nv_bfloat162* h2 = reinterpret_cast<__nv_bfloat162*>(g_hi);
    __nv_bfloat162* l2 = reinterpret_cast<__nv_bfloat162*>(g_lo);
    h2[base2 + 0] = __nv_bfloat162(hi[0], hi[1]);
    h2[base2 + 1] = __nv_bfloat162(hi[2], hi[3]);
    l2[base2 + 0] = __nv_bfloat162(lo[0], lo[1]);
    l2[base2 + 1] = __nv_bfloat162(lo[2], lo[3]);
}

// ---------------------------------------------------------------------------
// Kernel 2: bf16 mma.sync GEMM, 128x128 tile, BK=32, 2-stage cp.async pipe.
// D = Ahi*Bhi^T + Ahi*Blo^T + Alo*Bhi^T (fp32 acc), symmetric skip + mirror.
// 8 warps in 4(M) x 2(N); warp tile 32x64 = 2x8 m16n8 mma tiles.
// Round 11: __launch_bounds__(256,2) for 2 CTAs/SM; B fragments processed in
// two halves (bh[4]/bl[4]) to fit the 128-register cap without spills.
// ---------------------------------------------------------------------------
static constexpr int BM = 128, BN = 128, BK = 32;
static constexpr int NCHUNK = K / BK;                 // 16
static constexpr int LDS_STRIDE_B = 80;               // bytes per smem row (40 bf16)
static constexpr int TILE_BYTES = BM * LDS_STRIDE_B;  // 10240
static constexpr int STAGE_BYTES = 4 * TILE_BYTES;    // Ahi,Alo,Bhi,Blo = 40960
static constexpr int SMEM_TOTAL = 2 * STAGE_BYTES;    // 81920 (x2 CTAs = 160KB < 228KB)

__device__ __forceinline__ float leaky(float v) {
    return v >= 0.0f ? v : NEG_SLOPE * v;
}

// Issue cp.async for one 4-tile chunk (Ahi,Alo,Bhi,Blo; 128 rows x 32 bf16 each).
// 2048 x 16B over 256 threads = 8 per thread.
__device__ __forceinline__ void load_chunk(uint32_t sbase, int rowA, int rowB,
                                           int k0, int tid) {
    #pragma unroll
    for (int i = 0; i < 8; i++) {
        const int idx = tid + i * 256;        // 0..2047
        const int t = idx >> 9;               // tile 0..3
        const int idx2 = idx & 511;
        const int row = idx2 >> 2;            // 0..127
        const int c8 = idx2 & 3;              // 16B unit within 64B of row data
        const int r0 = (t < 2) ? rowA : rowB;
        const __nv_bfloat16* src = (t & 1) ? g_lo : g_hi;
        const void* g = (const void*)(src + (size_t)(r0 + row) * K + k0 + c8 * 8);
        const uint32_t s = sbase + t * TILE_BYTES + row * LDS_STRIDE_B + c8 * 16;
        cp_async16(s, g);
    }
}

__global__ void __launch_bounds__(256, 2) gemm_mma(float* __restrict__ C) {
    const int bx = blockIdx.x;
    const int by = blockIdx.y;
    if (bx < by) return;  // block-level upper triangle only

    extern __shared__ char smem[];
    const uint32_t sb = smem_u32(smem);
    const int tid = threadIdx.x;
    const int wid = tid >> 5;
    const int lane = tid & 31;
    const int wm = wid & 3;   // 0..3 -> 32-row slab
    const int wn = wid >> 2;  // 0..1 -> 64-col slab

    const int rowA = by * BM;
    const int rowB = bx * BN;

    float acc[2][8][4] = {};

    load_chunk(sb, rowA, rowB, 0, tid);
    cp_commit();

    for (int c = 0; c < NCHUNK; c++) {
        const int stage = c & 1;
        if (c + 1 < NCHUNK) {
            load_chunk(sb + ((c + 1) & 1) * STAGE_BYTES, rowA, rowB,
                       (c + 1) * BK, tid);
            cp_commit();
            cp_wait<1>();
        } else {
            cp_wait<0>();
        }
        __syncthreads();

        const uint32_t Ah = sb + stage * STAGE_BYTES;
        const uint32_t Al = Ah + TILE_BYTES;
        const uint32_t Bh = Ah + 2 * TILE_BYTES;
        const uint32_t Bl = Ah + 3 * TILE_BYTES;

        #pragma unroll
        for (int ks = 0; ks < 2; ks++) {
            uint32_t ah[2][4], al[2][4];
            #pragma unroll
            for (int mt = 0; mt < 2; mt++) {
                const int r = wm * 32 + mt * 16 + (lane & 15);
                const int colb = (ks * 16 + ((lane >> 4) << 3)) * 2;
                const uint32_t off = r * LDS_STRIDE_B + colb;
                ldsm_x4(ah[mt][0], ah[mt][1], ah[mt][2], ah[mt][3], Ah + off);
                ldsm_x4(al[mt][0], al[mt][1], al[mt][2], al[mt][3], Al + off);
            }
            // B fragments in two halves of 4 n-tiles to bound register pressure.
            #pragma unroll
            for (int nh = 0; nh < 2; nh++) {
                uint32_t bh[4][2], bl[4][2];
                #pragma unroll
                for (int j = 0; j < 4; j++) {
                    const int nt = nh * 4 + j;
                    const int r = wn * 64 + nt * 8 + (lane & 7);
                    const int colb = (ks * 16 + (((lane >> 3) & 1) << 3)) * 2;
                    const uint32_t off = r * LDS_STRIDE_B + colb;
                    ldsm_x2(bh[j][0], bh[j][1], Bh + off);
                    ldsm_x2(bl[j][0], bl[j][1], Bl + off);
                }
                #pragma unroll
                for (int mt = 0; mt < 2; mt++)
                    #pragma unroll
                    for (int j = 0; j < 4; j++) {
                        float* a = acc[mt][nh * 4 + j];
                        mma_bf16(a, ah[mt][0], ah[mt][1], ah[mt][2], ah[mt][3],
                                 bh[j][0], bh[j][1]);
                        mma_bf16(a, ah[mt][0], ah[mt][1], ah[mt][2], ah[mt][3],
                                 bl[j][0], bl[j][1]);
                        mma_bf16(a, al[mt][0], al[mt][1], al[mt][2], al[mt][3],
                                 bh[j][0], bh[j][1]);
                    }
            }
        }
        __syncthreads();  // all reads of this stage done before its next overwrite
    }

    // Epilogue: mma acc layout: c0,c1 -> (row, col+{0,1}); c2,c3 -> (row+8, ...).
    const int gr = lane >> 2;
    const int gc = (lane & 3) * 2;
    #pragma unroll
    for (int mt = 0; mt < 2; mt++) {
        #pragma unroll
        for (int nt = 0; nt < 8; nt++) {
            const float* a = acc[mt][nt];
            const int row = by * BM + wm * 32 + mt * 16 + gr;
            const int col = bx * BN + wn * 64 + nt * 8 + gc;
            const float v0 = leaky(a[0]), v1 = leaky(a[1]);
            const float v2 = leaky(a[2]), v3 = leaky(a[3]);
            *reinterpret_cast<float2*>(C + (size_t)row * M + col) = make_float2(v0, v1);
            *reinterpret_cast<float2*>(C + (size_t)(row + 8) * M + col) = make_float2(v2, v3);
            if (bx != by) {
                C[(size_t)col * M + row] = v0;
                C[(size_t)(col + 1) * M + row] = v1;
                C[(size_t)col * M + row + 8] = v2;
                C[(size_t)(col + 1) * M + row + 8] = v3;
            }
        }
    }
}

// ---------------------------------------------------------------------------
// Launch. d_in[0] = x (unused), d_in[1] = proto. Output 8192x8192 f32.
// ---------------------------------------------------------------------------
extern "C" void kernel_launch(void* const* d_in, const int* in_sizes, int n_in,
                              void* d_out, int out_size) {
    (void)in_sizes; (void)n_in; (void)out_size;
    const float* proto = (const float*)d_in[1];
    float* C = (float*)d_out;

    cudaFuncSetAttribute(gemm_mma, cudaFuncAttributeMaxDynamicSharedMemorySize,
                         SMEM_TOTAL);
    normalize_split<<<M, 128>>>(proto);
    gemm_mma<<<dim3(M / BN, M / BM), 256, SMEM_TOTAL>>>(C);
}